// round 3
// baseline (speedup 1.0000x reference)
#include <cuda_runtime.h>
#include <math.h>

// ---------------------------------------------------------------------------
// GCViT block: LN1 -> window partition -> KV proj -> global-query attention
// (+rel pos bias) -> proj -> residual -> LN2 -> MLP(GELU) -> residual
// Shapes: B=32 H=W=64 C=192 NH=6 hd=32 WS=8 N=64 hidden=768
// ---------------------------------------------------------------------------

#define TOKENS   131072          // B*H*W
#define CH       192
#define HIDDEN   768
#define NWIN     2048            // windows total
#define WN       64              // tokens per window
#define NHEADS   6
#define HD       32

// Scratch (device globals; allocation-free per harness rules)
__device__ float g_hwin[TOKENS * CH];        // LN1 output, window order
__device__ float g_kv  [TOKENS * 2 * CH];    // KV projection, window order
__device__ float g_ow  [TOKENS * CH];        // attention output, window order
__device__ float g_op  [TOKENS * CH];        // proj output, window order
__device__ float g_y   [TOKENS * CH];        // residual-1, original order
__device__ float g_h2  [TOKENS * CH];        // LN2 output, original order
__device__ float g_a1  [TOKENS * HIDDEN];    // fc1+gelu activations

// ---------------------------------------------------------------------------
__device__ __forceinline__ float warp_sum(float v) {
#pragma unroll
    for (int o = 16; o; o >>= 1) v += __shfl_xor_sync(0xffffffffu, v, o);
    return v;
}

// LN1 + window partition. warp-per-token; grid*block = TOKENS warps.
__global__ void ln1_win_kernel(const float* __restrict__ x,
                               const float* __restrict__ g,
                               const float* __restrict__ b,
                               float* __restrict__ hw) {
    int tok  = (blockIdx.x * blockDim.x + threadIdx.x) >> 5;
    int lane = threadIdx.x & 31;
    const float* xr = x + (size_t)tok * CH;
    float v[6], s = 0.f, s2 = 0.f;
#pragma unroll
    for (int j = 0; j < 6; j++) {
        float t = xr[lane + 32 * j];
        v[j] = t; s += t; s2 += t * t;
    }
    s = warp_sum(s); s2 = warp_sum(s2);
    float mean = s * (1.f / CH);
    float var  = s2 * (1.f / CH) - mean * mean;
    float inv  = rsqrtf(var + 1e-5f);

    int bi = tok >> 12;            // image
    int hh = (tok >> 6) & 63;
    int ww = tok & 63;
    size_t dst = ((size_t)(bi * 64 + ((hh >> 3) << 3) + (ww >> 3)) * WN
                  + ((hh & 7) << 3) + (ww & 7)) * CH;
#pragma unroll
    for (int j = 0; j < 6; j++) {
        int c = lane + 32 * j;
        hw[dst + c] = (v[j] - mean) * inv * g[c] + b[c];
    }
}

// residual + LN2 (window reverse on the fly). warp-per-token.
__global__ void resid_ln2_kernel(const float* __restrict__ x,
                                 const float* __restrict__ oproj,
                                 const float* __restrict__ g,
                                 const float* __restrict__ b,
                                 float* __restrict__ y,
                                 float* __restrict__ h2) {
    int tok  = (blockIdx.x * blockDim.x + threadIdx.x) >> 5;
    int lane = threadIdx.x & 31;
    int bi = tok >> 12;
    int hh = (tok >> 6) & 63;
    int ww = tok & 63;
    size_t win = ((size_t)(bi * 64 + ((hh >> 3) << 3) + (ww >> 3)) * WN
                  + ((hh & 7) << 3) + (ww & 7)) * CH;
    const float* xr = x + (size_t)tok * CH;
    const float* orow = oproj + win;
    float v[6], s = 0.f, s2 = 0.f;
#pragma unroll
    for (int j = 0; j < 6; j++) {
        int c = lane + 32 * j;
        float t = xr[c] + orow[c];
        v[j] = t; s += t; s2 += t * t;
        y[(size_t)tok * CH + c] = t;
    }
    s = warp_sum(s); s2 = warp_sum(s2);
    float mean = s * (1.f / CH);
    float var  = s2 * (1.f / CH) - mean * mean;
    float inv  = rsqrtf(var + 1e-5f);
#pragma unroll
    for (int j = 0; j < 6; j++) {
        int c = lane + 32 * j;
        h2[(size_t)tok * CH + c] = (v[j] - mean) * inv * g[c] + b[c];
    }
}

// ---------------------------------------------------------------------------
// Attention: block = one (window, head); 64 threads, thread n = query row n.
// ---------------------------------------------------------------------------
__global__ void attn_kernel(const float* __restrict__ kv,
                            const float* __restrict__ qg,
                            const float* __restrict__ rpb,
                            float* __restrict__ ow) {
    __shared__ float ks[WN][HD];
    __shared__ float vs[WN][HD];
    __shared__ float ss[WN][WN + 1];   // scores, stride 65 (conflict-free)
    __shared__ float bsh[225];

    const int head = blockIdx.x;
    const int wb   = blockIdx.y;
    const int tid  = threadIdx.x;
    const int bimg = wb >> 6;

    // cooperative coalesced load of K and V tiles (each 64x32 f32)
    const float* kvb = kv + (size_t)wb * WN * (2 * CH) + head * HD;
#pragma unroll
    for (int it = 0; it < 8; it++) {
        int i  = tid + it * 64;
        int m  = i >> 3;
        int d4 = (i & 7) * 4;
        *(float4*)&ks[m][d4] = *(const float4*)&kvb[(size_t)m * 384 + d4];
        *(float4*)&vs[m][d4] = *(const float4*)&kvb[(size_t)m * 384 + CH + d4];
    }
    for (int i = tid; i < 225; i += 64) bsh[i] = rpb[i * NHEADS + head];
    __syncthreads();

    // q row for this thread (scaled)
    float q[HD];
    const float* qr = qg + (((size_t)bimg * WN + tid) * NHEADS + head) * HD;
#pragma unroll
    for (int d = 0; d < HD; d++) q[d] = qr[d] * 0.17677669529663687f;

    const int ni = tid >> 3, nj = tid & 7;

    // scores + row max
    float mx = -1e30f;
#pragma unroll 8
    for (int m = 0; m < WN; m++) {
        float acc = 0.f;
#pragma unroll
        for (int d4 = 0; d4 < 8; d4++) {
            float4 kk = *(const float4*)&ks[m][d4 * 4];
            acc += q[d4 * 4 + 0] * kk.x + q[d4 * 4 + 1] * kk.y
                 + q[d4 * 4 + 2] * kk.z + q[d4 * 4 + 3] * kk.w;
        }
        int mi = m >> 3, mj = m & 7;
        acc += bsh[(ni - mi + 7) * 15 + (nj - mj + 7)];
        ss[tid][m] = acc;
        mx = fmaxf(mx, acc);
    }
    // exp + sum
    float sum = 0.f;
#pragma unroll 8
    for (int m = 0; m < WN; m++) {
        float e = expf(ss[tid][m] - mx);
        ss[tid][m] = e;
        sum += e;
    }
    const float inv = 1.f / sum;

    // P @ V
    float ov[HD];
#pragma unroll
    for (int d = 0; d < HD; d++) ov[d] = 0.f;
#pragma unroll 8
    for (int m = 0; m < WN; m++) {
        float p = ss[tid][m] * inv;
#pragma unroll
        for (int d4 = 0; d4 < 8; d4++) {
            float4 vv = *(const float4*)&vs[m][d4 * 4];
            ov[d4 * 4 + 0] += p * vv.x;
            ov[d4 * 4 + 1] += p * vv.y;
            ov[d4 * 4 + 2] += p * vv.z;
            ov[d4 * 4 + 3] += p * vv.w;
        }
    }
    float* orow = ow + ((size_t)wb * WN + tid) * CH + head * HD;
#pragma unroll
    for (int d4 = 0; d4 < 8; d4++) {
        float4 o4 = make_float4(ov[d4*4+0], ov[d4*4+1], ov[d4*4+2], ov[d4*4+3]);
        *(float4*)&orow[d4 * 4] = o4;
    }
}

// ---------------------------------------------------------------------------
// Register-tiled fp32 GEMM. C[M,N] = A[M,K] @ B[K,N] + bias (+ epilogue).
// EPI: 0 = bias, 1 = bias+GELU(exact), 2 = bias + residual add
// grid = (N/BN, M/BM), block = (BM/TM)*(BN/TN). All dims divide exactly.
// ---------------------------------------------------------------------------
template<int BM, int BN, int BK, int TM, int TN, int EPI>
__global__ void __launch_bounds__((BM / TM) * (BN / TN))
sgemm_kernel(const float* __restrict__ Ag, const float* __restrict__ Bg,
             const float* __restrict__ bias, const float* __restrict__ res,
             float* __restrict__ Cg, int N, int K) {
    constexpr int NT = (BM / TM) * (BN / TN);
    constexpr int TX = BN / TN;
    constexpr int A_IT = BM * BK / 4 / NT;
    constexpr int B_IT = BK * BN / 4 / NT;

    __shared__ float As[BK][BM + 4];
    __shared__ float Bs[BK][BN + 4];

    const int tid = threadIdx.x;
    const int tx = tid % TX;
    const int ty = tid / TX;
    const int bx = blockIdx.x, by = blockIdx.y;

    const float* Ab = Ag + (size_t)by * BM * K;

    float acc[TM][TN];
#pragma unroll
    for (int i = 0; i < TM; i++)
#pragma unroll
        for (int j = 0; j < TN; j++) acc[i][j] = 0.f;

    for (int k0 = 0; k0 < K; k0 += BK) {
#pragma unroll
        for (int it = 0; it < A_IT; it++) {
            int i  = tid + it * NT;
            int r  = i / (BK / 4);
            int c4 = i % (BK / 4);
            float4 v = *(const float4*)(Ab + (size_t)r * K + k0 + c4 * 4);
            As[c4 * 4 + 0][r] = v.x; As[c4 * 4 + 1][r] = v.y;
            As[c4 * 4 + 2][r] = v.z; As[c4 * 4 + 3][r] = v.w;
        }
#pragma unroll
        for (int it = 0; it < B_IT; it++) {
            int i  = tid + it * NT;
            int r  = i / (BN / 4);
            int c4 = i % (BN / 4);
            float4 v = *(const float4*)(Bg + (size_t)(k0 + r) * N + bx * BN + c4 * 4);
            *(float4*)&Bs[r][c4 * 4] = v;
        }
        __syncthreads();
#pragma unroll
        for (int k = 0; k < BK; k++) {
            float ra[TM], rb[TN];
#pragma unroll
            for (int i = 0; i < TM; i++) ra[i] = As[k][ty * TM + i];
#pragma unroll
            for (int j = 0; j < TN; j++) rb[j] = Bs[k][tx * TN + j];
#pragma unroll
            for (int i = 0; i < TM; i++)
#pragma unroll
                for (int j = 0; j < TN; j++) acc[i][j] += ra[i] * rb[j];
        }
        __syncthreads();
    }

#pragma unroll
    for (int i = 0; i < TM; i++) {
        size_t row = (size_t)by * BM + ty * TM + i;
#pragma unroll
        for (int j = 0; j < TN; j++) {
            int col = bx * BN + tx * TN + j;
            float v = acc[i][j] + bias[col];
            if (EPI == 1) v = 0.5f * v * (1.0f + erff(v * 0.70710678118654752f));
            if (EPI == 2) v += res[row * N + col];
            Cg[row * N + col] = v;
        }
    }
}

// ---------------------------------------------------------------------------
extern "C" void kernel_launch(void* const* d_in, const int* in_sizes, int n_in,
                              void* d_out, int out_size) {
    const float* x       = (const float*)d_in[0];
    const float* qg      = (const float*)d_in[1];
    const float* n1g     = (const float*)d_in[2];
    const float* n1b     = (const float*)d_in[3];
    const float* qkv_w   = (const float*)d_in[4];
    const float* qkv_b   = (const float*)d_in[5];
    const float* rpb     = (const float*)d_in[6];
    const float* proj_w  = (const float*)d_in[7];
    const float* proj_b  = (const float*)d_in[8];
    const float* n2g     = (const float*)d_in[9];
    const float* n2b     = (const float*)d_in[10];
    const float* fc1_w   = (const float*)d_in[11];
    const float* fc1_b   = (const float*)d_in[12];
    const float* fc2_w   = (const float*)d_in[13];
    const float* fc2_b   = (const float*)d_in[14];
    float* out = (float*)d_out;

    float *hwin, *kvb, *owb, *opb, *yb, *h2b, *a1b;
    cudaGetSymbolAddress((void**)&hwin, g_hwin);
    cudaGetSymbolAddress((void**)&kvb,  g_kv);
    cudaGetSymbolAddress((void**)&owb,  g_ow);
    cudaGetSymbolAddress((void**)&opb,  g_op);
    cudaGetSymbolAddress((void**)&yb,   g_y);
    cudaGetSymbolAddress((void**)&h2b,  g_h2);
    cudaGetSymbolAddress((void**)&a1b,  g_a1);

    const int lnBlocks = TOKENS / 8;   // 8 warps (tokens) per 256-thread block

    // 1. LN1 + window partition
    ln1_win_kernel<<<lnBlocks, 256>>>(x, n1g, n1b, hwin);

    // 2. KV GEMM: [131072,192] @ [192,384]
    sgemm_kernel<128, 128, 8, 8, 8, 0><<<dim3(384 / 128, TOKENS / 128), 256>>>(
        hwin, qkv_w, qkv_b, nullptr, kvb, 384, CH);

    // 3. attention per (head, window)
    attn_kernel<<<dim3(NHEADS, NWIN), WN>>>(kvb, qg, rpb, owb);

    // 4. proj GEMM: [131072,192] @ [192,192]
    sgemm_kernel<128, 64, 16, 8, 8, 0><<<dim3(CH / 64, TOKENS / 128), 128>>>(
        owb, proj_w, proj_b, nullptr, opb, CH, CH);

    // 5. residual + LN2 (window reverse)
    resid_ln2_kernel<<<lnBlocks, 256>>>(x, opb, n2g, n2b, yb, h2b);

    // 6. fc1 + GELU: [131072,192] @ [192,768]
    sgemm_kernel<128, 128, 8, 8, 8, 1><<<dim3(HIDDEN / 128, TOKENS / 128), 256>>>(
        h2b, fc1_w, fc1_b, nullptr, a1b, HIDDEN, CH);

    // 7. fc2 + residual -> out: [131072,768] @ [768,192]
    sgemm_kernel<128, 64, 16, 8, 8, 2><<<dim3(CH / 64, TOKENS / 128), 128>>>(
        a1b, fc2_w, fc2_b, yb, out, CH, HIDDEN);
}

// round 5
// speedup vs baseline: 2.5243x; 2.5243x over previous
#include <cuda_runtime.h>
#include <math.h>
#include <stdint.h>

// ---------------------------------------------------------------------------
// GCViT block, R4: GEMMs on tensor cores (tf32 mma.sync) + cp.async pipeline.
// Fix vs R3: correct PTX A-fragment register order (a1 <-> a2).
// Shapes: B=32 H=W=64 C=192 NH=6 hd=32 WS=8 N=64 hidden=768
// ---------------------------------------------------------------------------

#define TOKENS   131072
#define CH       192
#define HIDDEN   768
#define NWIN     2048
#define WN_TOK   64
#define NHEADS   6
#define HD       32

__device__ float g_hwin[TOKENS * CH];
__device__ float g_kv  [TOKENS * 2 * CH];
__device__ float g_ow  [TOKENS * CH];
__device__ float g_op  [TOKENS * CH];
__device__ float g_y   [TOKENS * CH];
__device__ float g_h2  [TOKENS * CH];
__device__ float g_a1  [TOKENS * HIDDEN];

// ---------------------------------------------------------------------------
__device__ __forceinline__ float warp_sum(float v) {
#pragma unroll
    for (int o = 16; o; o >>= 1) v += __shfl_xor_sync(0xffffffffu, v, o);
    return v;
}

__global__ void ln1_win_kernel(const float* __restrict__ x,
                               const float* __restrict__ g,
                               const float* __restrict__ b,
                               float* __restrict__ hw) {
    int tok  = (blockIdx.x * blockDim.x + threadIdx.x) >> 5;
    int lane = threadIdx.x & 31;
    const float* xr = x + (size_t)tok * CH;
    float v[6], s = 0.f, s2 = 0.f;
#pragma unroll
    for (int j = 0; j < 6; j++) {
        float t = xr[lane + 32 * j];
        v[j] = t; s += t; s2 += t * t;
    }
    s = warp_sum(s); s2 = warp_sum(s2);
    float mean = s * (1.f / CH);
    float var  = s2 * (1.f / CH) - mean * mean;
    float inv  = rsqrtf(var + 1e-5f);
    int bi = tok >> 12;
    int hh = (tok >> 6) & 63;
    int ww = tok & 63;
    size_t dst = ((size_t)(bi * 64 + ((hh >> 3) << 3) + (ww >> 3)) * WN_TOK
                  + ((hh & 7) << 3) + (ww & 7)) * CH;
#pragma unroll
    for (int j = 0; j < 6; j++) {
        int c = lane + 32 * j;
        hw[dst + c] = (v[j] - mean) * inv * g[c] + b[c];
    }
}

__global__ void resid_ln2_kernel(const float* __restrict__ x,
                                 const float* __restrict__ oproj,
                                 const float* __restrict__ g,
                                 const float* __restrict__ b,
                                 float* __restrict__ y,
                                 float* __restrict__ h2) {
    int tok  = (blockIdx.x * blockDim.x + threadIdx.x) >> 5;
    int lane = threadIdx.x & 31;
    int bi = tok >> 12;
    int hh = (tok >> 6) & 63;
    int ww = tok & 63;
    size_t win = ((size_t)(bi * 64 + ((hh >> 3) << 3) + (ww >> 3)) * WN_TOK
                  + ((hh & 7) << 3) + (ww & 7)) * CH;
    const float* xr = x + (size_t)tok * CH;
    const float* orow = oproj + win;
    float v[6], s = 0.f, s2 = 0.f;
#pragma unroll
    for (int j = 0; j < 6; j++) {
        int c = lane + 32 * j;
        float t = xr[c] + orow[c];
        v[j] = t; s += t; s2 += t * t;
        y[(size_t)tok * CH + c] = t;
    }
    s = warp_sum(s); s2 = warp_sum(s2);
    float mean = s * (1.f / CH);
    float var  = s2 * (1.f / CH) - mean * mean;
    float inv  = rsqrtf(var + 1e-5f);
#pragma unroll
    for (int j = 0; j < 6; j++) {
        int c = lane + 32 * j;
        h2[(size_t)tok * CH + c] = (v[j] - mean) * inv * g[c] + b[c];
    }
}

// ---------------------------------------------------------------------------
// Attention: block = one (window, head); 64 threads, thread n = query row n.
// ---------------------------------------------------------------------------
__global__ void attn_kernel(const float* __restrict__ kv,
                            const float* __restrict__ qg,
                            const float* __restrict__ rpb,
                            float* __restrict__ ow) {
    __shared__ float ks[WN_TOK][HD];
    __shared__ float vs[WN_TOK][HD];
    __shared__ float ss[WN_TOK][WN_TOK + 1];
    __shared__ float bsh[225];

    const int head = blockIdx.x;
    const int wb   = blockIdx.y;
    const int tid  = threadIdx.x;
    const int bimg = wb >> 6;

    const float* kvb = kv + (size_t)wb * WN_TOK * (2 * CH) + head * HD;
#pragma unroll
    for (int it = 0; it < 8; it++) {
        int i  = tid + it * 64;
        int m  = i >> 3;
        int d4 = (i & 7) * 4;
        *(float4*)&ks[m][d4] = *(const float4*)&kvb[(size_t)m * 384 + d4];
        *(float4*)&vs[m][d4] = *(const float4*)&kvb[(size_t)m * 384 + CH + d4];
    }
    for (int i = tid; i < 225; i += 64) bsh[i] = rpb[i * NHEADS + head];
    __syncthreads();

    float q[HD];
    const float* qr = qg + (((size_t)bimg * WN_TOK + tid) * NHEADS + head) * HD;
#pragma unroll
    for (int d = 0; d < HD; d++) q[d] = qr[d] * 0.17677669529663687f;

    const int ni = tid >> 3, nj = tid & 7;

    float mx = -1e30f;
#pragma unroll 8
    for (int m = 0; m < WN_TOK; m++) {
        float acc = 0.f;
#pragma unroll
        for (int d4 = 0; d4 < 8; d4++) {
            float4 kk = *(const float4*)&ks[m][d4 * 4];
            acc += q[d4 * 4 + 0] * kk.x + q[d4 * 4 + 1] * kk.y
                 + q[d4 * 4 + 2] * kk.z + q[d4 * 4 + 3] * kk.w;
        }
        int mi = m >> 3, mj = m & 7;
        acc += bsh[(ni - mi + 7) * 15 + (nj - mj + 7)];
        ss[tid][m] = acc;
        mx = fmaxf(mx, acc);
    }
    float sum = 0.f;
#pragma unroll 8
    for (int m = 0; m < WN_TOK; m++) {
        float e = expf(ss[tid][m] - mx);
        ss[tid][m] = e;
        sum += e;
    }
    const float inv = 1.f / sum;

    float ov[HD];
#pragma unroll
    for (int d = 0; d < HD; d++) ov[d] = 0.f;
#pragma unroll 8
    for (int m = 0; m < WN_TOK; m++) {
        float p = ss[tid][m] * inv;
#pragma unroll
        for (int d4 = 0; d4 < 8; d4++) {
            float4 vv = *(const float4*)&vs[m][d4 * 4];
            ov[d4 * 4 + 0] += p * vv.x;
            ov[d4 * 4 + 1] += p * vv.y;
            ov[d4 * 4 + 2] += p * vv.z;
            ov[d4 * 4 + 3] += p * vv.w;
        }
    }
    float* orow = ow + ((size_t)wb * WN_TOK + tid) * CH + head * HD;
#pragma unroll
    for (int d4 = 0; d4 < 8; d4++) {
        float4 o4 = make_float4(ov[d4*4+0], ov[d4*4+1], ov[d4*4+2], ov[d4*4+3]);
        *(float4*)&orow[d4 * 4] = o4;
    }
}

// ---------------------------------------------------------------------------
// tf32 tensor-core GEMM. C[M,N] = A[M,K] @ B[K,N] + bias (+epilogue).
// BM=128 fixed, BK=16, 4 warps (128 thr), warp tile 64 x WT_N.
// EPI: 0=bias  1=bias+GELU(exact)  2=bias+residual
// ---------------------------------------------------------------------------
__device__ __forceinline__ void cp_async8(uint32_t d, const void* s) {
    asm volatile("cp.async.ca.shared.global [%0], [%1], 8;\n" :: "r"(d), "l"(s));
}
__device__ __forceinline__ void cp_async16(uint32_t d, const void* s) {
    asm volatile("cp.async.cg.shared.global [%0], [%1], 16;\n" :: "r"(d), "l"(s));
}
__device__ __forceinline__ void mma_tf32(float* c, const uint32_t* a, const uint32_t* b) {
    asm volatile(
        "mma.sync.aligned.m16n8k8.row.col.f32.tf32.tf32.f32 "
        "{%0,%1,%2,%3}, {%4,%5,%6,%7}, {%8,%9}, {%0,%1,%2,%3};\n"
        : "+f"(c[0]), "+f"(c[1]), "+f"(c[2]), "+f"(c[3])
        : "r"(a[0]), "r"(a[1]), "r"(a[2]), "r"(a[3]), "r"(b[0]), "r"(b[1]));
}

template<int BN, int WT_N, int STAGES, int EPI>
__global__ void __launch_bounds__(128)
tgemm_kernel(const float* __restrict__ Ag, const float* __restrict__ Bg,
             const float* __restrict__ bias, const float* __restrict__ res,
             float* __restrict__ Cg, int N, int K) {
    constexpr int BM = 128, BK = 16, WT_M = 64;
    constexpr int NWN = BN / WT_N;            // 2
    constexpr int MT = WT_M / 16;             // 4
    constexpr int NT = WT_N / 8;              // 8 or 4
    constexpr int ASTR = 20;                  // bank = 4m+k -> conflict-free
    constexpr int BSTR = BN + 8;              // bank = 8k+n -> conflict-free
    constexpr int AWORDS = BM * ASTR;
    constexpr int BWORDS = BK * BSTR;
    constexpr int STW = AWORDS + BWORDS;
    constexpr int B_IT = (BK * BN / 4) / 128;

    __shared__ float sm[STW * STAGES];

    const int tid = threadIdx.x;
    const int w = tid >> 5, l = tid & 31;
    const int wm = w / NWN, wn = w % NWN;

    const float* Ab = Ag + (size_t)blockIdx.y * BM * K;
    const float* Bb = Bg + blockIdx.x * BN;
    const uint32_t smb = (uint32_t)__cvta_generic_to_shared(sm);

    const int ar  = tid >> 3, ac2 = tid & 7;               // A: 8B units
    const int brr = tid / (BN / 4), bc4 = tid % (BN / 4);  // B: 16B units

    float acc[MT][NT][4];
#pragma unroll
    for (int mt = 0; mt < MT; mt++)
#pragma unroll
        for (int nt = 0; nt < NT; nt++)
#pragma unroll
            for (int i = 0; i < 4; i++) acc[mt][nt][i] = 0.f;

    auto load = [&](int kc, int s) {
        const float* Asrc = Ab + kc * BK;
        uint32_t abase = smb + (uint32_t)(s * STW) * 4u;
#pragma unroll
        for (int it = 0; it < 8; it++) {
            int r = ar + it * 16;
            cp_async8(abase + (uint32_t)(r * ASTR + ac2 * 2) * 4u,
                      Asrc + (size_t)r * K + ac2 * 2);
        }
        const float* Bsrc = Bb + (size_t)kc * BK * N;
        uint32_t bbase = smb + (uint32_t)(s * STW + AWORDS) * 4u;
#pragma unroll
        for (int it = 0; it < B_IT; it++) {
            int rr = brr + it * (128 / (BN / 4));
            cp_async16(bbase + (uint32_t)(rr * BSTR + bc4 * 4) * 4u,
                       Bsrc + (size_t)rr * N + bc4 * 4);
        }
    };

    auto compute = [&](int s) {
        const float* A_s = sm + s * STW;
        const float* B_s = A_s + AWORDS;
#pragma unroll
        for (int ks = 0; ks < 2; ks++) {
            uint32_t af[MT][4], bf[NT][2];
            const int arow = wm * WT_M + (l >> 2);
            const int acol = ks * 8 + (l & 3);
#pragma unroll
            for (int mt = 0; mt < MT; mt++) {
                const float* p = A_s + (arow + mt * 16) * ASTR + acol;
                // PTX m16n8k8 tf32 A order: a0=(r,c) a1=(r+8,c) a2=(r,c+4) a3=(r+8,c+4)
                af[mt][0] = __float_as_uint(p[0]);
                af[mt][1] = __float_as_uint(p[8 * ASTR]);
                af[mt][2] = __float_as_uint(p[4]);
                af[mt][3] = __float_as_uint(p[8 * ASTR + 4]);
            }
            const int bcol = wn * WT_N + (l >> 2);
            const int brow = ks * 8 + (l & 3);
#pragma unroll
            for (int nt = 0; nt < NT; nt++) {
                const float* p = B_s + brow * BSTR + bcol + nt * 8;
                bf[nt][0] = __float_as_uint(p[0]);
                bf[nt][1] = __float_as_uint(p[4 * BSTR]);
            }
#pragma unroll
            for (int mt = 0; mt < MT; mt++)
#pragma unroll
                for (int nt = 0; nt < NT; nt++)
                    mma_tf32(acc[mt][nt], af[mt], bf[nt]);
        }
    };

    const int CHUNKS = K / BK;
#pragma unroll
    for (int s = 0; s < STAGES - 1; s++) {
        load(s, s);
        asm volatile("cp.async.commit_group;\n" ::: "memory");
    }
    for (int c = 0; c < CHUNKS; c++) {
        asm volatile("cp.async.wait_group %0;\n" :: "n"(STAGES - 2) : "memory");
        __syncthreads();
        if (c + STAGES - 1 < CHUNKS) load(c + STAGES - 1, (c + STAGES - 1) % STAGES);
        asm volatile("cp.async.commit_group;\n" ::: "memory");
        compute(c % STAGES);
        __syncthreads();
    }

    // epilogue
    const int row0 = blockIdx.y * BM + wm * WT_M + (l >> 2);
    const int col0 = blockIdx.x * BN + wn * WT_N + 2 * (l & 3);
#pragma unroll
    for (int mt = 0; mt < MT; mt++) {
#pragma unroll
        for (int h = 0; h < 2; h++) {
            size_t row = (size_t)row0 + mt * 16 + h * 8;
            float* crow = Cg + row * N;
            const float* rrow = res + row * N;
#pragma unroll
            for (int nt = 0; nt < NT; nt++) {
                int col = col0 + nt * 8;
                float v0 = acc[mt][nt][h * 2 + 0] + bias[col];
                float v1 = acc[mt][nt][h * 2 + 1] + bias[col + 1];
                if (EPI == 1) {
                    v0 = 0.5f * v0 * (1.0f + erff(v0 * 0.70710678118654752f));
                    v1 = 0.5f * v1 * (1.0f + erff(v1 * 0.70710678118654752f));
                }
                if (EPI == 2) { v0 += rrow[col]; v1 += rrow[col + 1]; }
                *(float2*)(crow + col) = make_float2(v0, v1);
            }
        }
    }
}

// ---------------------------------------------------------------------------
extern "C" void kernel_launch(void* const* d_in, const int* in_sizes, int n_in,
                              void* d_out, int out_size) {
    const float* x       = (const float*)d_in[0];
    const float* qg      = (const float*)d_in[1];
    const float* n1g     = (const float*)d_in[2];
    const float* n1b     = (const float*)d_in[3];
    const float* qkv_w   = (const float*)d_in[4];
    const float* qkv_b   = (const float*)d_in[5];
    const float* rpb     = (const float*)d_in[6];
    const float* proj_w  = (const float*)d_in[7];
    const float* proj_b  = (const float*)d_in[8];
    const float* n2g     = (const float*)d_in[9];
    const float* n2b     = (const float*)d_in[10];
    const float* fc1_w   = (const float*)d_in[11];
    const float* fc1_b   = (const float*)d_in[12];
    const float* fc2_w   = (const float*)d_in[13];
    const float* fc2_b   = (const float*)d_in[14];
    float* out = (float*)d_out;

    float *hwin, *kvb, *owb, *opb, *yb, *h2b, *a1b;
    cudaGetSymbolAddress((void**)&hwin, g_hwin);
    cudaGetSymbolAddress((void**)&kvb,  g_kv);
    cudaGetSymbolAddress((void**)&owb,  g_ow);
    cudaGetSymbolAddress((void**)&opb,  g_op);
    cudaGetSymbolAddress((void**)&yb,   g_y);
    cudaGetSymbolAddress((void**)&h2b,  g_h2);
    cudaGetSymbolAddress((void**)&a1b,  g_a1);

    const int lnBlocks = TOKENS / 8;

    // 1. LN1 + window partition
    ln1_win_kernel<<<lnBlocks, 256>>>(x, n1g, n1b, hwin);

    // 2. KV GEMM: [131072,192] @ [192,384]   (tf32 TC)
    tgemm_kernel<128, 64, 2, 0><<<dim3(384 / 128, TOKENS / 128), 128>>>(
        hwin, qkv_w, qkv_b, hwin, kvb, 384, CH);

    // 3. attention per (head, window)
    attn_kernel<<<dim3(NHEADS, NWIN), WN_TOK>>>(kvb, qg, rpb, owb);

    // 4. proj GEMM: [131072,192] @ [192,192]
    tgemm_kernel<64, 32, 3, 0><<<dim3(CH / 64, TOKENS / 128), 128>>>(
        owb, proj_w, proj_b, owb, opb, CH, CH);

    // 5. residual + LN2 (window reverse)
    resid_ln2_kernel<<<lnBlocks, 256>>>(x, opb, n2g, n2b, yb, h2b);

    // 6. fc1 + GELU: [131072,192] @ [192,768]
    tgemm_kernel<128, 64, 2, 1><<<dim3(HIDDEN / 128, TOKENS / 128), 128>>>(
        h2b, fc1_w, fc1_b, h2b, a1b, HIDDEN, CH);

    // 7. fc2 + residual -> out: [131072,768] @ [768,192]
    tgemm_kernel<64, 32, 3, 2><<<dim3(CH / 64, TOKENS / 128), 128>>>(
        a1b, fc2_w, fc2_b, yb, out, CH, HIDDEN);
}

// round 6
// speedup vs baseline: 3.2454x; 1.2856x over previous
#include <cuda_runtime.h>
#include <cuda_fp16.h>
#include <math.h>
#include <stdint.h>

// ---------------------------------------------------------------------------
// GCViT block, R6: GEMMs on f16 tensor cores (mma.m16n8k16 + ldmatrix),
// half activations, fp32 accumulate/epilogues.
// Shapes: B=32 H=W=64 C=192 NH=6 hd=32 WS=8 N=64 hidden=768
// ---------------------------------------------------------------------------

#define TOKENS   131072
#define CH       192
#define HIDDEN   768
#define NWIN     2048
#define WN_TOK   64
#define NHEADS   6
#define HD       32

__device__ __half g_hwin_h[TOKENS * CH];
__device__ float  g_kv   [TOKENS * 2 * CH];
__device__ __half g_ow_h [TOKENS * CH];
__device__ float  g_op   [TOKENS * CH];
__device__ float  g_y    [TOKENS * CH];
__device__ __half g_h2_h [TOKENS * CH];
__device__ __half g_a1_h [TOKENS * HIDDEN];
// transposed half weights: qkv[384][192] | proj[192][192] | fc1[768][192] | fc2[192][768]
__device__ __half g_wt[73728 + 36864 + 147456 + 147456];

// ---------------------------------------------------------------------------
__device__ __forceinline__ float warp_sum(float v) {
#pragma unroll
    for (int o = 16; o; o >>= 1) v += __shfl_xor_sync(0xffffffffu, v, o);
    return v;
}

// W[K][N] f32 -> Wt[N][K] half. block (32,8), grid (N/32, K/32)
__global__ void wconv_kernel(const float* __restrict__ W, __half* __restrict__ Wt,
                             int K, int N) {
    __shared__ float t[32][33];
    int k0 = blockIdx.y * 32, n0 = blockIdx.x * 32;
    int tx = threadIdx.x, ty = threadIdx.y;
#pragma unroll
    for (int i = 0; i < 32; i += 8)
        t[ty + i][tx] = W[(size_t)(k0 + ty + i) * N + n0 + tx];
    __syncthreads();
#pragma unroll
    for (int i = 0; i < 32; i += 8)
        Wt[(size_t)(n0 + ty + i) * K + k0 + tx] = __float2half(t[tx][ty + i]);
}

__global__ void ln1_win_kernel(const float* __restrict__ x,
                               const float* __restrict__ g,
                               const float* __restrict__ b,
                               __half* __restrict__ hw) {
    int tok  = (blockIdx.x * blockDim.x + threadIdx.x) >> 5;
    int lane = threadIdx.x & 31;
    const float* xr = x + (size_t)tok * CH;
    float v[6], s = 0.f, s2 = 0.f;
#pragma unroll
    for (int j = 0; j < 6; j++) {
        float t = xr[lane + 32 * j];
        v[j] = t; s += t; s2 += t * t;
    }
    s = warp_sum(s); s2 = warp_sum(s2);
    float mean = s * (1.f / CH);
    float var  = s2 * (1.f / CH) - mean * mean;
    float inv  = rsqrtf(var + 1e-5f);
    int bi = tok >> 12;
    int hh = (tok >> 6) & 63;
    int ww = tok & 63;
    size_t dst = ((size_t)(bi * 64 + ((hh >> 3) << 3) + (ww >> 3)) * WN_TOK
                  + ((hh & 7) << 3) + (ww & 7)) * CH;
#pragma unroll
    for (int j = 0; j < 6; j++) {
        int c = lane + 32 * j;
        hw[dst + c] = __float2half((v[j] - mean) * inv * g[c] + b[c]);
    }
}

__global__ void resid_ln2_kernel(const float* __restrict__ x,
                                 const float* __restrict__ oproj,
                                 const float* __restrict__ g,
                                 const float* __restrict__ b,
                                 float* __restrict__ y,
                                 __half* __restrict__ h2) {
    int tok  = (blockIdx.x * blockDim.x + threadIdx.x) >> 5;
    int lane = threadIdx.x & 31;
    int bi = tok >> 12;
    int hh = (tok >> 6) & 63;
    int ww = tok & 63;
    size_t win = ((size_t)(bi * 64 + ((hh >> 3) << 3) + (ww >> 3)) * WN_TOK
                  + ((hh & 7) << 3) + (ww & 7)) * CH;
    const float* xr = x + (size_t)tok * CH;
    const float* orow = oproj + win;
    float v[6], s = 0.f, s2 = 0.f;
#pragma unroll
    for (int j = 0; j < 6; j++) {
        int c = lane + 32 * j;
        float t = xr[c] + orow[c];
        v[j] = t; s += t; s2 += t * t;
        y[(size_t)tok * CH + c] = t;
    }
    s = warp_sum(s); s2 = warp_sum(s2);
    float mean = s * (1.f / CH);
    float var  = s2 * (1.f / CH) - mean * mean;
    float inv  = rsqrtf(var + 1e-5f);
#pragma unroll
    for (int j = 0; j < 6; j++) {
        int c = lane + 32 * j;
        h2[(size_t)tok * CH + c] = __float2half((v[j] - mean) * inv * g[c] + b[c]);
    }
}

// ---------------------------------------------------------------------------
// Attention: block = one (window, head); 64 threads, thread n = query row n.
// ---------------------------------------------------------------------------
__global__ void attn_kernel(const float* __restrict__ kv,
                            const float* __restrict__ qg,
                            const float* __restrict__ rpb,
                            __half* __restrict__ ow) {
    __shared__ float ks[WN_TOK][HD];
    __shared__ float vs[WN_TOK][HD];
    __shared__ float ss[WN_TOK][WN_TOK + 1];
    __shared__ float bsh[225];

    const int head = blockIdx.x;
    const int wb   = blockIdx.y;
    const int tid  = threadIdx.x;
    const int bimg = wb >> 6;

    const float* kvb = kv + (size_t)wb * WN_TOK * (2 * CH) + head * HD;
#pragma unroll
    for (int it = 0; it < 8; it++) {
        int i  = tid + it * 64;
        int m  = i >> 3;
        int d4 = (i & 7) * 4;
        *(float4*)&ks[m][d4] = *(const float4*)&kvb[(size_t)m * 384 + d4];
        *(float4*)&vs[m][d4] = *(const float4*)&kvb[(size_t)m * 384 + CH + d4];
    }
    for (int i = tid; i < 225; i += 64) bsh[i] = rpb[i * NHEADS + head];
    __syncthreads();

    float q[HD];
    const float* qr = qg + (((size_t)bimg * WN_TOK + tid) * NHEADS + head) * HD;
#pragma unroll
    for (int d = 0; d < HD; d++) q[d] = qr[d] * 0.17677669529663687f;

    const int ni = tid >> 3, nj = tid & 7;

    float mx = -1e30f;
#pragma unroll 8
    for (int m = 0; m < WN_TOK; m++) {
        float acc = 0.f;
#pragma unroll
        for (int d4 = 0; d4 < 8; d4++) {
            float4 kk = *(const float4*)&ks[m][d4 * 4];
            acc += q[d4 * 4 + 0] * kk.x + q[d4 * 4 + 1] * kk.y
                 + q[d4 * 4 + 2] * kk.z + q[d4 * 4 + 3] * kk.w;
        }
        int mi = m >> 3, mj = m & 7;
        acc += bsh[(ni - mi + 7) * 15 + (nj - mj + 7)];
        ss[tid][m] = acc;
        mx = fmaxf(mx, acc);
    }
    float sum = 0.f;
#pragma unroll 8
    for (int m = 0; m < WN_TOK; m++) {
        float e = expf(ss[tid][m] - mx);
        ss[tid][m] = e;
        sum += e;
    }
    const float inv = 1.f / sum;

    float ov[HD];
#pragma unroll
    for (int d = 0; d < HD; d++) ov[d] = 0.f;
#pragma unroll 8
    for (int m = 0; m < WN_TOK; m++) {
        float p = ss[tid][m] * inv;
#pragma unroll
        for (int d4 = 0; d4 < 8; d4++) {
            float4 vv = *(const float4*)&vs[m][d4 * 4];
            ov[d4 * 4 + 0] += p * vv.x;
            ov[d4 * 4 + 1] += p * vv.y;
            ov[d4 * 4 + 2] += p * vv.z;
            ov[d4 * 4 + 3] += p * vv.w;
        }
    }
    __half* orow = ow + ((size_t)wb * WN_TOK + tid) * CH + head * HD;
#pragma unroll
    for (int d2 = 0; d2 < 16; d2++)
        *(__half2*)(orow + d2 * 2) = __floats2half2_rn(ov[d2 * 2], ov[d2 * 2 + 1]);
}

// ---------------------------------------------------------------------------
// f16 tensor-core GEMM. C[M,N] = A[M,K] @ Wt[N,K]^T + bias (+epilogue).
// BM=128, BN=64, BK=32, 3 stages, 4 warps (2x2), warp tile 64x32.
// EPI: 0=bias->f32  1=bias+GELU->half  2=bias+residual->f32
// ---------------------------------------------------------------------------
__device__ __forceinline__ void cp_async16(uint32_t d, const void* s) {
    asm volatile("cp.async.cg.shared.global [%0], [%1], 16;\n" :: "r"(d), "l"(s));
}
__device__ __forceinline__ void ldsm4(uint32_t* r, uint32_t addr) {
    asm volatile("ldmatrix.sync.aligned.m8n8.x4.shared.b16 {%0,%1,%2,%3}, [%4];\n"
                 : "=r"(r[0]), "=r"(r[1]), "=r"(r[2]), "=r"(r[3]) : "r"(addr));
}
__device__ __forceinline__ void mma_f16(float* c, const uint32_t* a, const uint32_t* b) {
    asm volatile(
        "mma.sync.aligned.m16n8k16.row.col.f32.f16.f16.f32 "
        "{%0,%1,%2,%3}, {%4,%5,%6,%7}, {%8,%9}, {%0,%1,%2,%3};\n"
        : "+f"(c[0]), "+f"(c[1]), "+f"(c[2]), "+f"(c[3])
        : "r"(a[0]), "r"(a[1]), "r"(a[2]), "r"(a[3]), "r"(b[0]), "r"(b[1]));
}

template<int EPI>
__global__ void __launch_bounds__(128)
hgemm_kernel(const __half* __restrict__ Ag, const __half* __restrict__ Bt,
             const float* __restrict__ bias, const float* __restrict__ res,
             void* __restrict__ Cg, int N, int K) {
    constexpr int BM = 128, BN = 64, BK = 32, STG = 3;
    constexpr int STR = BK + 8;                 // 40 halves (80B) rows
    constexpr int AH = BM * STR;                // 5120 halves
    constexpr int BH = BN * STR;                // 2560 halves
    constexpr int STW = AH + BH;                // halves per stage

    __shared__ __half sm[STW * STG];

    const int tid = threadIdx.x;
    const int w = tid >> 5, l = tid & 31;
    const int wm = w >> 1, wn = w & 1;

    const __half* Ab = Ag + (size_t)blockIdx.y * BM * K;
    const __half* Bb = Bt + (size_t)blockIdx.x * BN * K;
    const uint32_t smb = (uint32_t)__cvta_generic_to_shared(sm);

    const int lr = tid >> 2, lc = tid & 3;      // 16B-chunk coords

    // per-thread fragment byte offsets (within stage)
    const uint32_t a_off = (uint32_t)(((wm * 64 + (l & 15)) * STR + (l >> 4) * 8) * 2);
    const int n_off = (l & 7) + ((l >> 4) << 3);
    const int k_off = ((l >> 3) & 1) * 8;
    const uint32_t b_off = (uint32_t)((AH + (wn * 32 + n_off) * STR + k_off) * 2);

    float acc[4][4][4];
#pragma unroll
    for (int mt = 0; mt < 4; mt++)
#pragma unroll
        for (int nt = 0; nt < 4; nt++)
#pragma unroll
            for (int i = 0; i < 4; i++) acc[mt][nt][i] = 0.f;

    auto load = [&](int kc, int s) {
        uint32_t base = smb + (uint32_t)(s * STW) * 2u;
#pragma unroll
        for (int it = 0; it < 4; it++) {        // A: 128 rows x 4 chunks
            int i = tid + it * 128;
            int r = i >> 2, c4 = i & 3;
            cp_async16(base + (uint32_t)(r * STR + c4 * 8) * 2u,
                       Ab + (size_t)r * K + kc * BK + c4 * 8);
        }
        uint32_t bbase = base + (uint32_t)AH * 2u;
#pragma unroll
        for (int it = 0; it < 2; it++) {        // B: 64 rows x 4 chunks
            int i = tid + it * 128;
            int r = i >> 2, c4 = i & 3;
            cp_async16(bbase + (uint32_t)(r * STR + c4 * 8) * 2u,
                       Bb + (size_t)r * K + kc * BK + c4 * 8);
        }
    };

    auto compute = [&](int s) {
        uint32_t stage = smb + (uint32_t)(s * STW) * 2u;
#pragma unroll
        for (int ks = 0; ks < 2; ks++) {
            uint32_t af[4][4], bf[4][2];
#pragma unroll
            for (int mt = 0; mt < 4; mt++)
                ldsm4(af[mt], stage + a_off + (uint32_t)((mt * 16 * STR + ks * 16) * 2));
#pragma unroll
            for (int ntp = 0; ntp < 2; ntp++) {
                uint32_t t4[4];
                ldsm4(t4, stage + b_off + (uint32_t)((ntp * 16 * STR + ks * 16) * 2));
                bf[ntp * 2 + 0][0] = t4[0]; bf[ntp * 2 + 0][1] = t4[1];
                bf[ntp * 2 + 1][0] = t4[2]; bf[ntp * 2 + 1][1] = t4[3];
            }
#pragma unroll
            for (int mt = 0; mt < 4; mt++)
#pragma unroll
                for (int nt = 0; nt < 4; nt++)
                    mma_f16(acc[mt][nt], af[mt], bf[nt]);
        }
    };

    const int CHUNKS = K / BK;
#pragma unroll
    for (int s = 0; s < STG - 1; s++) {
        load(s, s);
        asm volatile("cp.async.commit_group;\n" ::: "memory");
    }
    for (int c = 0; c < CHUNKS; c++) {
        asm volatile("cp.async.wait_group %0;\n" :: "n"(STG - 2) : "memory");
        __syncthreads();
        if (c + STG - 1 < CHUNKS) load(c + STG - 1, (c + STG - 1) % STG);
        asm volatile("cp.async.commit_group;\n" ::: "memory");
        compute(c % STG);
        __syncthreads();
    }

    // epilogue
    const int row0 = blockIdx.y * BM + wm * 64 + (l >> 2);
    const int col0 = blockIdx.x * BN + wn * 32 + 2 * (l & 3);
#pragma unroll
    for (int mt = 0; mt < 4; mt++) {
#pragma unroll
        for (int h = 0; h < 2; h++) {
            size_t row = (size_t)row0 + mt * 16 + h * 8;
#pragma unroll
            for (int nt = 0; nt < 4; nt++) {
                int col = col0 + nt * 8;
                float v0 = acc[mt][nt][h * 2 + 0] + bias[col];
                float v1 = acc[mt][nt][h * 2 + 1] + bias[col + 1];
                if (EPI == 1) {
                    v0 = 0.5f * v0 * (1.0f + erff(v0 * 0.70710678118654752f));
                    v1 = 0.5f * v1 * (1.0f + erff(v1 * 0.70710678118654752f));
                    *(__half2*)((__half*)Cg + row * N + col) = __floats2half2_rn(v0, v1);
                } else {
                    if (EPI == 2) {
                        v0 += res[row * N + col];
                        v1 += res[row * N + col + 1];
                    }
                    *(float2*)((float*)Cg + row * N + col) = make_float2(v0, v1);
                }
            }
        }
    }
}

// ---------------------------------------------------------------------------
extern "C" void kernel_launch(void* const* d_in, const int* in_sizes, int n_in,
                              void* d_out, int out_size) {
    const float* x       = (const float*)d_in[0];
    const float* qg      = (const float*)d_in[1];
    const float* n1g     = (const float*)d_in[2];
    const float* n1b     = (const float*)d_in[3];
    const float* qkv_w   = (const float*)d_in[4];
    const float* qkv_b   = (const float*)d_in[5];
    const float* rpb     = (const float*)d_in[6];
    const float* proj_w  = (const float*)d_in[7];
    const float* proj_b  = (const float*)d_in[8];
    const float* n2g     = (const float*)d_in[9];
    const float* n2b     = (const float*)d_in[10];
    const float* fc1_w   = (const float*)d_in[11];
    const float* fc1_b   = (const float*)d_in[12];
    const float* fc2_w   = (const float*)d_in[13];
    const float* fc2_b   = (const float*)d_in[14];
    float* out = (float*)d_out;

    __half *hwin, *owh, *h2h, *a1h, *wt;
    float *kvb, *opb, *yb;
    cudaGetSymbolAddress((void**)&hwin, g_hwin_h);
    cudaGetSymbolAddress((void**)&kvb,  g_kv);
    cudaGetSymbolAddress((void**)&owh,  g_ow_h);
    cudaGetSymbolAddress((void**)&opb,  g_op);
    cudaGetSymbolAddress((void**)&yb,   g_y);
    cudaGetSymbolAddress((void**)&h2h,  g_h2_h);
    cudaGetSymbolAddress((void**)&a1h,  g_a1_h);
    cudaGetSymbolAddress((void**)&wt,   g_wt);

    __half* qkv_t = wt;
    __half* proj_t = wt + 73728;
    __half* fc1_t = wt + 110592;
    __half* fc2_t = wt + 258048;

    // weight conversion (tiny)
    wconv_kernel<<<dim3(384 / 32, 192 / 32), dim3(32, 8)>>>(qkv_w, qkv_t, CH, 384);
    wconv_kernel<<<dim3(192 / 32, 192 / 32), dim3(32, 8)>>>(proj_w, proj_t, CH, CH);
    wconv_kernel<<<dim3(768 / 32, 192 / 32), dim3(32, 8)>>>(fc1_w, fc1_t, CH, HIDDEN);
    wconv_kernel<<<dim3(192 / 32, 768 / 32), dim3(32, 8)>>>(fc2_w, fc2_t, HIDDEN, CH);

    const int lnBlocks = TOKENS / 8;

    // 1. LN1 + window partition (half out)
    ln1_win_kernel<<<lnBlocks, 256>>>(x, n1g, n1b, hwin);

    // 2. KV GEMM: [131072,192] @ [192,384] -> f32
    hgemm_kernel<0><<<dim3(384 / 64, TOKENS / 128), 128>>>(
        hwin, qkv_t, qkv_b, nullptr, kvb, 384, CH);

    // 3. attention (half out)
    attn_kernel<<<dim3(NHEADS, NWIN), WN_TOK>>>(kvb, qg, rpb, owh);

    // 4. proj GEMM: [131072,192] @ [192,192] -> f32
    hgemm_kernel<0><<<dim3(CH / 64, TOKENS / 128), 128>>>(
        owh, proj_t, proj_b, nullptr, opb, CH, CH);

    // 5. residual + LN2 (y f32, h2 half)
    resid_ln2_kernel<<<lnBlocks, 256>>>(x, opb, n2g, n2b, yb, h2h);

    // 6. fc1 + GELU: [131072,192] @ [192,768] -> half
    hgemm_kernel<1><<<dim3(HIDDEN / 64, TOKENS / 128), 128>>>(
        h2h, fc1_t, fc1_b, nullptr, a1h, HIDDEN, CH);

    // 7. fc2 + residual -> out: [131072,768] @ [768,192] -> f32
    hgemm_kernel<2><<<dim3(CH / 64, TOKENS / 128), 128>>>(
        a1h, fc2_t, fc2_b, yb, out, CH, HIDDEN);
}